// round 9
// baseline (speedup 1.0000x reference)
#include <cuda_runtime.h>
#include <cuda_bf16.h>
#include <cstdint>

// ---------------- problem dims ----------------
#define MDIM 8192
#define NDIM 4096
#define KDIM 4096

// ---------------- tiling ----------------
#define BM 128
#define BN 128
#define BK 64                              // K elements per chunk (bf16): 128B per row
#define ROWB 144                           // padded row stride (128B data + 16B pad)
#define STAGES 3
#define NCHUNK (KDIM / BK)                 // 64
#define A_STAGE (BM * ROWB)                // 18432 B
#define B_STAGE (BN * ROWB)                // 18432 B
#define STAGE_BYTES (A_STAGE + B_STAGE)    // 36864 B
#define SMEM_DYN (STAGES * STAGE_BYTES)    // 110592 B -> 2 CTAs/SM
#define THREADS 256                        // 8 warps, warp tile 32x64 (R7 winner)

// ---------------- bf16 staging (static device globals: no allocation) ----------------
__device__ __nv_bfloat16 g_A[(size_t)MDIM * KDIM];   // 64 MB
__device__ __nv_bfloat16 g_B[(size_t)NDIM * KDIM];   // 32 MB

// ---------------- PTX helpers (base-ISA: cp.async / ldmatrix / mma.sync bf16) -------
__device__ __forceinline__ uint32_t smem_u32(const void* p) {
    uint32_t a;
    asm("{ .reg .u64 t; cvta.to.shared.u64 t, %1; cvt.u32.u64 %0, t; }" : "=r"(a) : "l"(p));
    return a;
}

__device__ __forceinline__ void cp16(uint32_t dst, const void* src) {
    asm volatile("cp.async.cg.shared.global [%0], [%1], 16;" :: "r"(dst), "l"(src));
}
__device__ __forceinline__ void cp_commit() {
    asm volatile("cp.async.commit_group;" ::: "memory");
}
template <int N>
__device__ __forceinline__ void cp_wait() {
    asm volatile("cp.async.wait_group %0;" :: "n"(N) : "memory");
}

__device__ __forceinline__ void ldsm4(uint32_t* r, uint32_t addr) {
    asm volatile("ldmatrix.sync.aligned.m8n8.x4.shared.b16 {%0,%1,%2,%3}, [%4];"
                 : "=r"(r[0]), "=r"(r[1]), "=r"(r[2]), "=r"(r[3])
                 : "r"(addr));
}

__device__ __forceinline__ void mma_bf16(float* d, const uint32_t* a, const uint32_t* b) {
    asm volatile("mma.sync.aligned.m16n8k16.row.col.f32.bf16.bf16.f32 "
                 "{%0,%1,%2,%3}, {%4,%5,%6,%7}, {%8,%9}, {%0,%1,%2,%3};"
                 : "+f"(d[0]), "+f"(d[1]), "+f"(d[2]), "+f"(d[3])
                 : "r"(a[0]), "r"(a[1]), "r"(a[2]), "r"(a[3]), "r"(b[0]), "r"(b[1]));
}

// ---------------- conversion kernels (int8-valued -> bf16, exact) ----------------
__global__ void __launch_bounds__(256) cvt_x_kernel(const int4* __restrict__ x) {
    size_t i = (size_t)blockIdx.x * blockDim.x + threadIdx.x;   // over MDIM*KDIM/4
    int4 v = x[i];
    union { __nv_bfloat162 h2[2]; uint2 u; } o;
    o.h2[0] = __floats2bfloat162_rn((float)v.x, (float)v.y);
    o.h2[1] = __floats2bfloat162_rn((float)v.z, (float)v.w);
    reinterpret_cast<uint2*>(g_A)[i] = o.u;
}

__global__ void __launch_bounds__(256) cvt_w_kernel(const float4* __restrict__ w) {
    size_t i = (size_t)blockIdx.x * blockDim.x + threadIdx.x;   // over NDIM*KDIM/4
    float4 v = w[i];
    union { __nv_bfloat162 h2[2]; uint2 u; } o;
    o.h2[0] = __floats2bfloat162_rn(v.x, v.y);
    o.h2[1] = __floats2bfloat162_rn(v.z, v.w);
    reinterpret_cast<uint2*>(g_B)[i] = o.u;
}

// ---------------- GEMM kernel ----------------
__device__ __forceinline__ int clip8(int v) {
    return v < -128 ? -128 : (v > 127 ? 127 : v);
}

__global__ void __launch_bounds__(THREADS, 2)
hmma_gemm_kernel(const float* __restrict__ bias,
                 const float* __restrict__ alpha_p,
                 float* __restrict__ out) {
    extern __shared__ int8_t smem[];
    const uint32_t sbase = smem_u32(smem);

    const int tid  = threadIdx.x;
    const int lane = tid & 31;
    const int wid  = tid >> 5;       // 0..7
    const int wm   = wid >> 1;       // 0..3  (M warps, 32 rows each)
    const int wn   = wid & 1;        // 0..1  (N warps, 64 cols each)
    const int m_base = blockIdx.y * BM;
    const int n_base = blockIdx.x * BN;

    float acc[2][8][4];
    #pragma unroll
    for (int i = 0; i < 2; i++)
        #pragma unroll
        for (int j = 0; j < 8; j++)
            #pragma unroll
            for (int k = 0; k < 4; k++) acc[i][j][k] = 0.0f;

    // --- ldmatrix per-thread address components (padded 144B rows) ---
    const uint32_t arow   = (uint32_t)(wm * 32 + (lane & 15));
    const uint32_t akb_hi = (uint32_t)(lane >> 4);                 // 0/1 (8-element k half)
    const uint32_t a_off  = arow * ROWB + akb_hi * 16u;           // + s*32 + i*(16*ROWB)

    const uint32_t brow   = (uint32_t)(wn * 64 + (lane & 7) + ((lane >> 4) << 3));
    const uint32_t bkb_hi = (uint32_t)((lane >> 3) & 1);
    const uint32_t b_off  = brow * ROWB + bkb_hi * 16u;           // + s*32 + j*(16*ROWB)

    // --- stage loader: 2048 x 16B chunks, 8 per thread ---
    auto load_stage = [&](int kc, int st) {
        const uint32_t sb = sbase + (uint32_t)st * STAGE_BYTES;
        const int kel = kc * BK;                                   // k element offset
        #pragma unroll
        for (int i = 0; i < 8; i++) {
            int ch = tid + THREADS * i;
            if (ch < 1024) {   // A: 1024 chunks (branch uniform: i<4)
                int row = ch >> 3, kb = ch & 7;
                cp16(sb + (uint32_t)row * ROWB + (uint32_t)kb * 16u,
                     g_A + (size_t)(m_base + row) * KDIM + kel + kb * 8);
            } else {           // B: 1024 chunks
                int c2 = ch - 1024;
                int row = c2 >> 3, kb = c2 & 7;
                cp16(sb + A_STAGE + (uint32_t)row * ROWB + (uint32_t)kb * 16u,
                     g_B + (size_t)(n_base + row) * KDIM + kel + kb * 8);
            }
        }
        cp_commit();
    };

    // --- prologue: 2 stages in flight ---
    load_stage(0, 0);
    load_stage(1, 1);

    // --- mainloop ---
    int st = 0;
    for (int c = 0; c < NCHUNK; c++) {
        cp_wait<1>();
        __syncthreads();

        // Issue next stage's DMA FIRST (before compute) to maximize overlap.
        // Slot (c+2)%3 was last read in iter c-1; this iteration's barrier above
        // orders those reads before these cp.async writes.
        if (c + 2 < NCHUNK) load_stage(c + 2, (c + 2) % STAGES);
        else                cp_commit();   // keep wait_group counting aligned

        const uint32_t sb = sbase + (uint32_t)st * STAGE_BYTES;
        #pragma unroll
        for (int s = 0; s < 4; s++) {                      // 4 k16 steps per chunk
            uint32_t af[2][4];
            ldsm4(af[0], sb + a_off + (uint32_t)s * 32u);
            ldsm4(af[1], sb + a_off + (uint32_t)s * 32u + 16u * ROWB);
            #pragma unroll
            for (int j = 0; j < 4; j++) {                  // 4 n16 pairs = 64 n
                uint32_t bf[4];
                ldsm4(bf, sb + A_STAGE + b_off + (uint32_t)s * 32u + (uint32_t)j * (16u * ROWB));
                mma_bf16(acc[0][2 * j],     af[0], bf);
                mma_bf16(acc[0][2 * j + 1], af[0], bf + 2);
                mma_bf16(acc[1][2 * j],     af[1], bf);
                mma_bf16(acc[1][2 * j + 1], af[1], bf + 2);
            }
        }

        st = (st + 1 == STAGES) ? 0 : st + 1;
    }

    // --- epilogue: y = clip(round_half_even(acc*alpha + bias)), stored as FLOAT32 ---
    const float alphav = *alpha_p;
    const int g = lane >> 2, t = lane & 3;
    #pragma unroll
    for (int i = 0; i < 2; i++) {
        const size_t row0 = (size_t)(m_base + wm * 32 + i * 16 + g);
        #pragma unroll
        for (int j = 0; j < 8; j++) {
            const int nc = n_base + wn * 64 + j * 8 + 2 * t;
            const float b0 = __ldg(bias + nc);
            const float b1 = __ldg(bias + nc + 1);
            const float* a = acc[i][j];
            int v0 = clip8(__float2int_rn(__fadd_rn(__fmul_rn(a[0], alphav), b0)));
            int v1 = clip8(__float2int_rn(__fadd_rn(__fmul_rn(a[1], alphav), b1)));
            int v2 = clip8(__float2int_rn(__fadd_rn(__fmul_rn(a[2], alphav), b0)));
            int v3 = clip8(__float2int_rn(__fadd_rn(__fmul_rn(a[3], alphav), b1)));
            float2 lo = make_float2((float)v0, (float)v1);
            float2 hi = make_float2((float)v2, (float)v3);
            *reinterpret_cast<float2*>(out + row0 * NDIM + nc) = lo;
            *reinterpret_cast<float2*>(out + (row0 + 8) * NDIM + nc) = hi;
        }
    }
}

// ---------------- host launch ----------------
extern "C" void kernel_launch(void* const* d_in, const int* in_sizes, int n_in,
                              void* d_out, int out_size) {
    const int*   x     = (const int*)d_in[0];
    const float* w     = (const float*)d_in[1];
    const float* bias  = (const float*)d_in[2];
    const float* alpha = (const float*)d_in[3];
    float*       out   = (float*)d_out;

    // stage bf16 conversions
    cvt_x_kernel<<<(unsigned)(((size_t)MDIM * KDIM / 4) / 256), 256>>>((const int4*)x);
    cvt_w_kernel<<<(unsigned)(((size_t)NDIM * KDIM / 4) / 256), 256>>>((const float4*)w);

    // set every call (non-stream API, capture-safe; no static guards per harness rules)
    cudaFuncSetAttribute(hmma_gemm_kernel,
                         cudaFuncAttributeMaxDynamicSharedMemorySize, SMEM_DYN);

    dim3 grid(NDIM / BN, MDIM / BM);   // (32, 64) = 2048 CTAs
    hmma_gemm_kernel<<<grid, THREADS, SMEM_DYN>>>(bias, alpha, out);
}

// round 10
// speedup vs baseline: 1.1411x; 1.1411x over previous
#include <cuda_runtime.h>
#include <cuda_bf16.h>
#include <cstdint>

// ---------------- problem dims ----------------
#define MDIM 8192
#define NDIM 4096
#define KDIM 4096

// ---------------- tiling ----------------
#define BM 128
#define BN 128
#define BK 64                              // K elements per chunk (bf16): 128B per row
#define ROWB 144                           // padded row stride (128B data + 16B pad)
#define STAGES 3
#define NCHUNK (KDIM / BK)                 // 64
#define A_STAGE (BM * ROWB)                // 18432 B
#define B_STAGE (BN * ROWB)                // 18432 B
#define STAGE_BYTES (A_STAGE + B_STAGE)    // 36864 B
#define SMEM_DYN (STAGES * STAGE_BYTES)    // 110592 B -> 2 CTAs/SM
#define THREADS 256                        // 8 warps, warp tile 32x64 (R7 winner)

// ---------------- bf16 staging (static device globals: no allocation) ----------------
__device__ __nv_bfloat16 g_A[(size_t)MDIM * KDIM];   // 64 MB
__device__ __nv_bfloat16 g_B[(size_t)NDIM * KDIM];   // 32 MB

// ---------------- PTX helpers (base-ISA: cp.async / ldmatrix / mma.sync bf16) -------
__device__ __forceinline__ uint32_t smem_u32(const void* p) {
    uint32_t a;
    asm("{ .reg .u64 t; cvta.to.shared.u64 t, %1; cvt.u32.u64 %0, t; }" : "=r"(a) : "l"(p));
    return a;
}

__device__ __forceinline__ void cp16(uint32_t dst, const void* src) {
    asm volatile("cp.async.cg.shared.global [%0], [%1], 16;" :: "r"(dst), "l"(src));
}
__device__ __forceinline__ void cp_commit() {
    asm volatile("cp.async.commit_group;" ::: "memory");
}
template <int N>
__device__ __forceinline__ void cp_wait() {
    asm volatile("cp.async.wait_group %0;" :: "n"(N) : "memory");
}

__device__ __forceinline__ void ldsm4(uint32_t* r, uint32_t addr) {
    asm volatile("ldmatrix.sync.aligned.m8n8.x4.shared.b16 {%0,%1,%2,%3}, [%4];"
                 : "=r"(r[0]), "=r"(r[1]), "=r"(r[2]), "=r"(r[3])
                 : "r"(addr));
}

__device__ __forceinline__ void mma_bf16(float* d, const uint32_t* a, const uint32_t* b) {
    asm volatile("mma.sync.aligned.m16n8k16.row.col.f32.bf16.bf16.f32 "
                 "{%0,%1,%2,%3}, {%4,%5,%6,%7}, {%8,%9}, {%0,%1,%2,%3};"
                 : "+f"(d[0]), "+f"(d[1]), "+f"(d[2]), "+f"(d[3])
                 : "r"(a[0]), "r"(a[1]), "r"(a[2]), "r"(a[3]), "r"(b[0]), "r"(b[1]));
}

// ---------------- conversion kernels (int8-valued -> bf16, exact) ----------------
// 32B per thread (2 x int4), MLP=2, 512-thread blocks for HBM saturation.
__global__ void __launch_bounds__(512) cvt_x_kernel(const int4* __restrict__ x) {
    size_t i = 2 * ((size_t)blockIdx.x * blockDim.x + threadIdx.x);   // over MDIM*KDIM/4
    int4 v0 = x[i];
    int4 v1 = x[i + 1];
    union { __nv_bfloat162 h2[2]; uint2 u; } o0, o1;
    o0.h2[0] = __floats2bfloat162_rn((float)v0.x, (float)v0.y);
    o0.h2[1] = __floats2bfloat162_rn((float)v0.z, (float)v0.w);
    o1.h2[0] = __floats2bfloat162_rn((float)v1.x, (float)v1.y);
    o1.h2[1] = __floats2bfloat162_rn((float)v1.z, (float)v1.w);
    reinterpret_cast<uint2*>(g_A)[i]     = o0.u;
    reinterpret_cast<uint2*>(g_A)[i + 1] = o1.u;
}

__global__ void __launch_bounds__(512) cvt_w_kernel(const float4* __restrict__ w) {
    size_t i = 2 * ((size_t)blockIdx.x * blockDim.x + threadIdx.x);   // over NDIM*KDIM/4
    float4 v0 = w[i];
    float4 v1 = w[i + 1];
    union { __nv_bfloat162 h2[2]; uint2 u; } o0, o1;
    o0.h2[0] = __floats2bfloat162_rn(v0.x, v0.y);
    o0.h2[1] = __floats2bfloat162_rn(v0.z, v0.w);
    o1.h2[0] = __floats2bfloat162_rn(v1.x, v1.y);
    o1.h2[1] = __floats2bfloat162_rn(v1.z, v1.w);
    reinterpret_cast<uint2*>(g_B)[i]     = o0.u;
    reinterpret_cast<uint2*>(g_B)[i + 1] = o1.u;
}

// ---------------- GEMM kernel (R7 winner, verbatim) ----------------
__device__ __forceinline__ int clip8(int v) {
    return v < -128 ? -128 : (v > 127 ? 127 : v);
}

__global__ void __launch_bounds__(THREADS, 2)
hmma_gemm_kernel(const float* __restrict__ bias,
                 const float* __restrict__ alpha_p,
                 float* __restrict__ out) {
    extern __shared__ int8_t smem[];
    const uint32_t sbase = smem_u32(smem);

    const int tid  = threadIdx.x;
    const int lane = tid & 31;
    const int wid  = tid >> 5;       // 0..7
    const int wm   = wid >> 1;       // 0..3  (M warps, 32 rows each)
    const int wn   = wid & 1;        // 0..1  (N warps, 64 cols each)
    const int m_base = blockIdx.y * BM;
    const int n_base = blockIdx.x * BN;

    float acc[2][8][4];
    #pragma unroll
    for (int i = 0; i < 2; i++)
        #pragma unroll
        for (int j = 0; j < 8; j++)
            #pragma unroll
            for (int k = 0; k < 4; k++) acc[i][j][k] = 0.0f;

    // --- ldmatrix per-thread address components (padded 144B rows) ---
    const uint32_t arow   = (uint32_t)(wm * 32 + (lane & 15));
    const uint32_t akb_hi = (uint32_t)(lane >> 4);                 // 0/1 (8-element k half)
    const uint32_t a_off  = arow * ROWB + akb_hi * 16u;           // + s*32 + i*(16*ROWB)

    const uint32_t brow   = (uint32_t)(wn * 64 + (lane & 7) + ((lane >> 4) << 3));
    const uint32_t bkb_hi = (uint32_t)((lane >> 3) & 1);
    const uint32_t b_off  = brow * ROWB + bkb_hi * 16u;           // + s*32 + j*(16*ROWB)

    // --- stage loader: 2048 x 16B chunks, 8 per thread ---
    auto load_stage = [&](int kc, int st) {
        const uint32_t sb = sbase + (uint32_t)st * STAGE_BYTES;
        const int kel = kc * BK;                                   // k element offset
        #pragma unroll
        for (int i = 0; i < 8; i++) {
            int ch = tid + THREADS * i;
            if (ch < 1024) {   // A: 1024 chunks (branch uniform: i<4)
                int row = ch >> 3, kb = ch & 7;
                cp16(sb + (uint32_t)row * ROWB + (uint32_t)kb * 16u,
                     g_A + (size_t)(m_base + row) * KDIM + kel + kb * 8);
            } else {           // B: 1024 chunks
                int c2 = ch - 1024;
                int row = c2 >> 3, kb = c2 & 7;
                cp16(sb + A_STAGE + (uint32_t)row * ROWB + (uint32_t)kb * 16u,
                     g_B + (size_t)(n_base + row) * KDIM + kel + kb * 8);
            }
        }
        cp_commit();
    };

    // --- prologue: 2 stages in flight ---
    load_stage(0, 0);
    load_stage(1, 1);

    // --- mainloop (R7 ordering: compute first, then issue next DMA) ---
    int st = 0;
    for (int c = 0; c < NCHUNK; c++) {
        cp_wait<1>();
        __syncthreads();

        const uint32_t sb = sbase + (uint32_t)st * STAGE_BYTES;
        #pragma unroll
        for (int s = 0; s < 4; s++) {                      // 4 k16 steps per chunk
            uint32_t af[2][4];
            ldsm4(af[0], sb + a_off + (uint32_t)s * 32u);
            ldsm4(af[1], sb + a_off + (uint32_t)s * 32u + 16u * ROWB);
            #pragma unroll
            for (int j = 0; j < 4; j++) {                  // 4 n16 pairs = 64 n
                uint32_t bf[4];
                ldsm4(bf, sb + A_STAGE + b_off + (uint32_t)s * 32u + (uint32_t)j * (16u * ROWB));
                mma_bf16(acc[0][2 * j],     af[0], bf);
                mma_bf16(acc[0][2 * j + 1], af[0], bf + 2);
                mma_bf16(acc[1][2 * j],     af[1], bf);
                mma_bf16(acc[1][2 * j + 1], af[1], bf + 2);
            }
        }

        // slot (c+2)%3 was last read in iter c-1, ordered by this iter's top barrier
        if (c + 2 < NCHUNK) load_stage(c + 2, (c + 2) % STAGES);
        else                cp_commit();   // keep wait_group counting aligned
        st = (st + 1 == STAGES) ? 0 : st + 1;
    }

    // --- epilogue: y = clip(round_half_even(acc*alpha + bias)), stored as FLOAT32 ---
    const float alphav = *alpha_p;
    const int g = lane >> 2, t = lane & 3;
    #pragma unroll
    for (int i = 0; i < 2; i++) {
        const size_t row0 = (size_t)(m_base + wm * 32 + i * 16 + g);
        #pragma unroll
        for (int j = 0; j < 8; j++) {
            const int nc = n_base + wn * 64 + j * 8 + 2 * t;
            const float b0 = __ldg(bias + nc);
            const float b1 = __ldg(bias + nc + 1);
            const float* a = acc[i][j];
            int v0 = clip8(__float2int_rn(__fadd_rn(__fmul_rn(a[0], alphav), b0)));
            int v1 = clip8(__float2int_rn(__fadd_rn(__fmul_rn(a[1], alphav), b1)));
            int v2 = clip8(__float2int_rn(__fadd_rn(__fmul_rn(a[2], alphav), b0)));
            int v3 = clip8(__float2int_rn(__fadd_rn(__fmul_rn(a[3], alphav), b1)));
            float2 lo = make_float2((float)v0, (float)v1);
            float2 hi = make_float2((float)v2, (float)v3);
            *reinterpret_cast<float2*>(out + row0 * NDIM + nc) = lo;
            *reinterpret_cast<float2*>(out + (row0 + 8) * NDIM + nc) = hi;
        }
    }
}

// ---------------- host launch ----------------
extern "C" void kernel_launch(void* const* d_in, const int* in_sizes, int n_in,
                              void* d_out, int out_size) {
    const int*   x     = (const int*)d_in[0];
    const float* w     = (const float*)d_in[1];
    const float* bias  = (const float*)d_in[2];
    const float* alpha = (const float*)d_in[3];
    float*       out   = (float*)d_out;

    // stage bf16 conversions (32B/thread, 512-thread blocks)
    cvt_x_kernel<<<(unsigned)(((size_t)MDIM * KDIM / 8) / 512), 512>>>((const int4*)x);
    cvt_w_kernel<<<(unsigned)(((size_t)NDIM * KDIM / 8) / 512), 512>>>((const float4*)w);

    // set every call (non-stream API, capture-safe; no static guards per harness rules)
    cudaFuncSetAttribute(hmma_gemm_kernel,
                         cudaFuncAttributeMaxDynamicSharedMemorySize, SMEM_DYN);

    dim3 grid(NDIM / BN, MDIM / BM);   // (32, 64) = 2048 CTAs
    hmma_gemm_kernel<<<grid, THREADS, SMEM_DYN>>>(bias, alpha, out);
}

// round 11
// speedup vs baseline: 1.1478x; 1.0059x over previous
#include <cuda_runtime.h>
#include <cuda_bf16.h>
#include <cstdint>

// ---------------- problem dims ----------------
#define MDIM 8192
#define NDIM 4096
#define KDIM 4096

// ---------------- tiling ----------------
#define BM 128
#define BN 128
#define BK 64                              // K elements per chunk (bf16): 128B per row
#define ROWB 144                           // padded row stride (128B data + 16B pad)
#define STAGES 3
#define NCHUNK (KDIM / BK)                 // 64
#define A_STAGE (BM * ROWB)                // 18432 B
#define B_STAGE (BN * ROWB)                // 18432 B
#define STAGE_BYTES (A_STAGE + B_STAGE)    // 36864 B
#define SMEM_DYN (STAGES * STAGE_BYTES)    // 110592 B -> 2 CTAs/SM
#define THREADS 256                        // 8 warps, warp tile 32x64 (R7/R10 winner)

// ---------------- bf16 staging (static device globals: no allocation) ----------------
__device__ __nv_bfloat16 g_A[(size_t)MDIM * KDIM];   // 64 MB
__device__ __nv_bfloat16 g_B[(size_t)NDIM * KDIM];   // 32 MB

// ---------------- PTX helpers (base-ISA: cp.async / ldmatrix / mma.sync bf16) -------
__device__ __forceinline__ uint32_t smem_u32(const void* p) {
    uint32_t a;
    asm("{ .reg .u64 t; cvta.to.shared.u64 t, %1; cvt.u32.u64 %0, t; }" : "=r"(a) : "l"(p));
    return a;
}

__device__ __forceinline__ void cp16(uint32_t dst, const void* src) {
    asm volatile("cp.async.cg.shared.global [%0], [%1], 16;" :: "r"(dst), "l"(src));
}
__device__ __forceinline__ void cp_commit() {
    asm volatile("cp.async.commit_group;" ::: "memory");
}
template <int N>
__device__ __forceinline__ void cp_wait() {
    asm volatile("cp.async.wait_group %0;" :: "n"(N) : "memory");
}

__device__ __forceinline__ void ldsm4(uint32_t* r, uint32_t addr) {
    asm volatile("ldmatrix.sync.aligned.m8n8.x4.shared.b16 {%0,%1,%2,%3}, [%4];"
                 : "=r"(r[0]), "=r"(r[1]), "=r"(r[2]), "=r"(r[3])
                 : "r"(addr));
}

__device__ __forceinline__ void mma_bf16(float* d, const uint32_t* a, const uint32_t* b) {
    asm volatile("mma.sync.aligned.m16n8k16.row.col.f32.bf16.bf16.f32 "
                 "{%0,%1,%2,%3}, {%4,%5,%6,%7}, {%8,%9}, {%0,%1,%2,%3};"
                 : "+f"(d[0]), "+f"(d[1]), "+f"(d[2]), "+f"(d[3])
                 : "r"(a[0]), "r"(a[1]), "r"(a[2]), "r"(a[3]), "r"(b[0]), "r"(b[1]));
}

// ---------------- fused conversion kernel (int8-valued -> bf16, exact) ----------------
// One launch converts both x (int32->bf16) and w (fp32->bf16).
// 64B in per thread (4 x 16B chunks), MLP=4, 512-thread blocks.
// x: MDIM*KDIM/4 = 8388608 int4 chunks  -> 4096 blocks (2048 chunks each)
// w: NDIM*KDIM/4 = 4194304 float4 chunks -> 2048 blocks
#define CVT_XBLOCKS 4096
#define CVT_WBLOCKS 2048

__global__ void __launch_bounds__(512) cvt_fused_kernel(const int4* __restrict__ x,
                                                        const float4* __restrict__ w) {
    const unsigned b = blockIdx.x;
    if (b < CVT_XBLOCKS) {
        const size_t base = (size_t)b * 2048 + threadIdx.x;
        int4 v[4];
        #pragma unroll
        for (int k = 0; k < 4; k++) v[k] = x[base + (size_t)k * 512];
        #pragma unroll
        for (int k = 0; k < 4; k++) {
            union { __nv_bfloat162 h2[2]; uint2 u; } o;
            o.h2[0] = __floats2bfloat162_rn((float)v[k].x, (float)v[k].y);
            o.h2[1] = __floats2bfloat162_rn((float)v[k].z, (float)v[k].w);
            reinterpret_cast<uint2*>(g_A)[base + (size_t)k * 512] = o.u;
        }
    } else {
        const size_t base = (size_t)(b - CVT_XBLOCKS) * 2048 + threadIdx.x;
        float4 v[4];
        #pragma unroll
        for (int k = 0; k < 4; k++) v[k] = w[base + (size_t)k * 512];
        #pragma unroll
        for (int k = 0; k < 4; k++) {
            union { __nv_bfloat162 h2[2]; uint2 u; } o;
            o.h2[0] = __floats2bfloat162_rn(v[k].x, v[k].y);
            o.h2[1] = __floats2bfloat162_rn(v[k].z, v[k].w);
            reinterpret_cast<uint2*>(g_B)[base + (size_t)k * 512] = o.u;
        }
    }
}

// ---------------- GEMM kernel (R10 winner, verbatim) ----------------
__device__ __forceinline__ int clip8(int v) {
    return v < -128 ? -128 : (v > 127 ? 127 : v);
}

__global__ void __launch_bounds__(THREADS, 2)
hmma_gemm_kernel(const float* __restrict__ bias,
                 const float* __restrict__ alpha_p,
                 float* __restrict__ out) {
    extern __shared__ int8_t smem[];
    const uint32_t sbase = smem_u32(smem);

    const int tid  = threadIdx.x;
    const int lane = tid & 31;
    const int wid  = tid >> 5;       // 0..7
    const int wm   = wid >> 1;       // 0..3  (M warps, 32 rows each)
    const int wn   = wid & 1;        // 0..1  (N warps, 64 cols each)
    const int m_base = blockIdx.y * BM;
    const int n_base = blockIdx.x * BN;

    float acc[2][8][4];
    #pragma unroll
    for (int i = 0; i < 2; i++)
        #pragma unroll
        for (int j = 0; j < 8; j++)
            #pragma unroll
            for (int k = 0; k < 4; k++) acc[i][j][k] = 0.0f;

    // --- ldmatrix per-thread address components (padded 144B rows) ---
    const uint32_t arow   = (uint32_t)(wm * 32 + (lane & 15));
    const uint32_t akb_hi = (uint32_t)(lane >> 4);                 // 0/1 (8-element k half)
    const uint32_t a_off  = arow * ROWB + akb_hi * 16u;           // + s*32 + i*(16*ROWB)

    const uint32_t brow   = (uint32_t)(wn * 64 + (lane & 7) + ((lane >> 4) << 3));
    const uint32_t bkb_hi = (uint32_t)((lane >> 3) & 1);
    const uint32_t b_off  = brow * ROWB + bkb_hi * 16u;           // + s*32 + j*(16*ROWB)

    // --- stage loader: 2048 x 16B chunks, 8 per thread ---
    auto load_stage = [&](int kc, int st) {
        const uint32_t sb = sbase + (uint32_t)st * STAGE_BYTES;
        const int kel = kc * BK;                                   // k element offset
        #pragma unroll
        for (int i = 0; i < 8; i++) {
            int ch = tid + THREADS * i;
            if (ch < 1024) {   // A: 1024 chunks (branch uniform: i<4)
                int row = ch >> 3, kb = ch & 7;
                cp16(sb + (uint32_t)row * ROWB + (uint32_t)kb * 16u,
                     g_A + (size_t)(m_base + row) * KDIM + kel + kb * 8);
            } else {           // B: 1024 chunks
                int c2 = ch - 1024;
                int row = c2 >> 3, kb = c2 & 7;
                cp16(sb + A_STAGE + (uint32_t)row * ROWB + (uint32_t)kb * 16u,
                     g_B + (size_t)(n_base + row) * KDIM + kel + kb * 8);
            }
        }
        cp_commit();
    };

    // --- prologue: 2 stages in flight ---
    load_stage(0, 0);
    load_stage(1, 1);

    // --- mainloop (compute first, then issue next DMA) ---
    int st = 0;
    for (int c = 0; c < NCHUNK; c++) {
        cp_wait<1>();
        __syncthreads();

        const uint32_t sb = sbase + (uint32_t)st * STAGE_BYTES;
        #pragma unroll
        for (int s = 0; s < 4; s++) {                      // 4 k16 steps per chunk
            uint32_t af[2][4];
            ldsm4(af[0], sb + a_off + (uint32_t)s * 32u);
            ldsm4(af[1], sb + a_off + (uint32_t)s * 32u + 16u * ROWB);
            #pragma unroll
            for (int j = 0; j < 4; j++) {                  // 4 n16 pairs = 64 n
                uint32_t bf[4];
                ldsm4(bf, sb + A_STAGE + b_off + (uint32_t)s * 32u + (uint32_t)j * (16u * ROWB));
                mma_bf16(acc[0][2 * j],     af[0], bf);
                mma_bf16(acc[0][2 * j + 1], af[0], bf + 2);
                mma_bf16(acc[1][2 * j],     af[1], bf);
                mma_bf16(acc[1][2 * j + 1], af[1], bf + 2);
            }
        }

        // slot (c+2)%3 was last read in iter c-1, ordered by this iter's top barrier
        if (c + 2 < NCHUNK) load_stage(c + 2, (c + 2) % STAGES);
        else                cp_commit();   // keep wait_group counting aligned
        st = (st + 1 == STAGES) ? 0 : st + 1;
    }

    // --- epilogue: y = clip(round_half_even(acc*alpha + bias)), stored as FLOAT32 ---
    const float alphav = *alpha_p;
    const int g = lane >> 2, t = lane & 3;
    #pragma unroll
    for (int i = 0; i < 2; i++) {
        const size_t row0 = (size_t)(m_base + wm * 32 + i * 16 + g);
        #pragma unroll
        for (int j = 0; j < 8; j++) {
            const int nc = n_base + wn * 64 + j * 8 + 2 * t;
            const float b0 = __ldg(bias + nc);
            const float b1 = __ldg(bias + nc + 1);
            const float* a = acc[i][j];
            int v0 = clip8(__float2int_rn(__fadd_rn(__fmul_rn(a[0], alphav), b0)));
            int v1 = clip8(__float2int_rn(__fadd_rn(__fmul_rn(a[1], alphav), b1)));
            int v2 = clip8(__float2int_rn(__fadd_rn(__fmul_rn(a[2], alphav), b0)));
            int v3 = clip8(__float2int_rn(__fadd_rn(__fmul_rn(a[3], alphav), b1)));
            float2 lo = make_float2((float)v0, (float)v1);
            float2 hi = make_float2((float)v2, (float)v3);
            *reinterpret_cast<float2*>(out + row0 * NDIM + nc) = lo;
            *reinterpret_cast<float2*>(out + (row0 + 8) * NDIM + nc) = hi;
        }
    }
}

// ---------------- host launch ----------------
extern "C" void kernel_launch(void* const* d_in, const int* in_sizes, int n_in,
                              void* d_out, int out_size) {
    const int*   x     = (const int*)d_in[0];
    const float* w     = (const float*)d_in[1];
    const float* bias  = (const float*)d_in[2];
    const float* alpha = (const float*)d_in[3];
    float*       out   = (float*)d_out;

    // single fused bf16 conversion launch (x + w)
    cvt_fused_kernel<<<CVT_XBLOCKS + CVT_WBLOCKS, 512>>>((const int4*)x, (const float4*)w);

    // set every call (non-stream API, capture-safe; no static guards per harness rules)
    cudaFuncSetAttribute(hmma_gemm_kernel,
                         cudaFuncAttributeMaxDynamicSharedMemorySize, SMEM_DYN);

    dim3 grid(NDIM / BN, MDIM / BM);   // (32, 64) = 2048 CTAs
    hmma_gemm_kernel<<<grid, THREADS, SMEM_DYN>>>(bias, alpha, out);
}

// round 12
// speedup vs baseline: 1.1823x; 1.0301x over previous
#include <cuda_runtime.h>
#include <cuda_bf16.h>
#include <cstdint>

// ---------------- problem dims ----------------
#define MDIM 8192
#define NDIM 4096
#define KDIM 4096

// ---------------- tiling ----------------
#define BM 128
#define BN 128
#define BK 64                              // K elements per chunk (bf16): 128B per row
#define ROWB 144                           // padded row stride (128B data + 16B pad)
#define STAGES 3
#define NCHUNK (KDIM / BK)                 // 64
#define A_STAGE (BM * ROWB)                // 18432 B
#define B_STAGE (BN * ROWB)                // 18432 B
#define STAGE_BYTES (A_STAGE + B_STAGE)    // 36864 B
#define SMEM_DYN (STAGES * STAGE_BYTES)    // 110592 B -> 2 CTAs/SM
#define THREADS 256                        // 8 warps, warp tile 32x64

// ---------------- bf16 staging (static device globals: no allocation) ----------------
__device__ __nv_bfloat16 g_A[(size_t)MDIM * KDIM];   // 64 MB
__device__ __nv_bfloat16 g_B[(size_t)NDIM * KDIM];   // 32 MB

// ---------------- PTX helpers (base-ISA: cp.async / ldmatrix / mma.sync bf16) -------
__device__ __forceinline__ uint32_t smem_u32(const void* p) {
    uint32_t a;
    asm("{ .reg .u64 t; cvta.to.shared.u64 t, %1; cvt.u32.u64 %0, t; }" : "=r"(a) : "l"(p));
    return a;
}

__device__ __forceinline__ void cp16(uint32_t dst, const void* src) {
    asm volatile("cp.async.cg.shared.global [%0], [%1], 16;" :: "r"(dst), "l"(src));
}
__device__ __forceinline__ void cp_commit() {
    asm volatile("cp.async.commit_group;" ::: "memory");
}
template <int N>
__device__ __forceinline__ void cp_wait() {
    asm volatile("cp.async.wait_group %0;" :: "n"(N) : "memory");
}

__device__ __forceinline__ void ldsm4(uint32_t* r, uint32_t addr) {
    asm volatile("ldmatrix.sync.aligned.m8n8.x4.shared.b16 {%0,%1,%2,%3}, [%4];"
                 : "=r"(r[0]), "=r"(r[1]), "=r"(r[2]), "=r"(r[3])
                 : "r"(addr));
}

__device__ __forceinline__ void mma_bf16(float* d, const uint32_t* a, const uint32_t* b) {
    asm volatile("mma.sync.aligned.m16n8k16.row.col.f32.bf16.bf16.f32 "
                 "{%0,%1,%2,%3}, {%4,%5,%6,%7}, {%8,%9}, {%0,%1,%2,%3};"
                 : "+f"(d[0]), "+f"(d[1]), "+f"(d[2]), "+f"(d[3])
                 : "r"(a[0]), "r"(a[1]), "r"(a[2]), "r"(a[3]), "r"(b[0]), "r"(b[1]));
}

// ---------------- fused conversion kernel (int8-valued -> bf16, exact) ----------------
#define CVT_XBLOCKS 4096
#define CVT_WBLOCKS 2048

__global__ void __launch_bounds__(512) cvt_fused_kernel(const int4* __restrict__ x,
                                                        const float4* __restrict__ w) {
    const unsigned b = blockIdx.x;
    if (b < CVT_XBLOCKS) {
        const size_t base = (size_t)b * 2048 + threadIdx.x;
        int4 v[4];
        #pragma unroll
        for (int k = 0; k < 4; k++) v[k] = x[base + (size_t)k * 512];
        #pragma unroll
        for (int k = 0; k < 4; k++) {
            union { __nv_bfloat162 h2[2]; uint2 u; } o;
            o.h2[0] = __floats2bfloat162_rn((float)v[k].x, (float)v[k].y);
            o.h2[1] = __floats2bfloat162_rn((float)v[k].z, (float)v[k].w);
            reinterpret_cast<uint2*>(g_A)[base + (size_t)k * 512] = o.u;
        }
    } else {
        const size_t base = (size_t)(b - CVT_XBLOCKS) * 2048 + threadIdx.x;
        float4 v[4];
        #pragma unroll
        for (int k = 0; k < 4; k++) v[k] = w[base + (size_t)k * 512];
        #pragma unroll
        for (int k = 0; k < 4; k++) {
            union { __nv_bfloat162 h2[2]; uint2 u; } o;
            o.h2[0] = __floats2bfloat162_rn(v[k].x, v[k].y);
            o.h2[1] = __floats2bfloat162_rn(v[k].z, v[k].w);
            reinterpret_cast<uint2*>(g_B)[base + (size_t)k * 512] = o.u;
        }
    }
}

// ---------------- GEMM kernel ----------------
__device__ __forceinline__ int clip8(int v) {
    return v < -128 ? -128 : (v > 127 ? 127 : v);
}

__global__ void __launch_bounds__(THREADS, 2)
hmma_gemm_kernel(const float* __restrict__ bias,
                 const float* __restrict__ alpha_p,
                 float* __restrict__ out) {
    extern __shared__ int8_t smem[];
    const uint32_t sbase = smem_u32(smem);

    const int tid  = threadIdx.x;
    const int lane = tid & 31;
    const int wid  = tid >> 5;       // 0..7
    const int wm   = wid >> 1;       // 0..3  (M warps, 32 rows each)
    const int wn   = wid & 1;        // 0..1  (N warps, 64 cols each)
    const int m_base = blockIdx.y * BM;
    const int n_base = blockIdx.x * BN;

    float acc[2][8][4];
    #pragma unroll
    for (int i = 0; i < 2; i++)
        #pragma unroll
        for (int j = 0; j < 8; j++)
            #pragma unroll
            for (int k = 0; k < 4; k++) acc[i][j][k] = 0.0f;

    // --- ldmatrix per-thread address components (padded 144B rows) ---
    const uint32_t arow   = (uint32_t)(wm * 32 + (lane & 15));
    const uint32_t akb_hi = (uint32_t)(lane >> 4);                 // 0/1 (8-element k half)
    const uint32_t a_off  = arow * ROWB + akb_hi * 16u;           // + s*32 + i*(16*ROWB)

    const uint32_t brow   = (uint32_t)(wn * 64 + (lane & 7) + ((lane >> 4) << 3));
    const uint32_t bkb_hi = (uint32_t)((lane >> 3) & 1);
    const uint32_t b_off  = brow * ROWB + bkb_hi * 16u;           // + s*32 + j*(16*ROWB)

    // --- one slice of a stage load: 2 chunks (of this thread's 8) ---
    // slice i covers chunk indices ch = tid + THREADS*(2*slice) and + THREADS*(2*slice+1)
    auto load_slice = [&](int kc, int st, int slice) {
        const uint32_t sb = sbase + (uint32_t)st * STAGE_BYTES;
        const int kel = kc * BK;
        #pragma unroll
        for (int q = 0; q < 2; q++) {
            int ch = tid + THREADS * (2 * slice + q);
            if (ch < 1024) {   // A: 1024 chunks (uniform: slice<2)
                int row = ch >> 3, kb = ch & 7;
                cp16(sb + (uint32_t)row * ROWB + (uint32_t)kb * 16u,
                     g_A + (size_t)(m_base + row) * KDIM + kel + kb * 8);
            } else {           // B: 1024 chunks
                int c2 = ch - 1024;
                int row = c2 >> 3, kb = c2 & 7;
                cp16(sb + A_STAGE + (uint32_t)row * ROWB + (uint32_t)kb * 16u,
                     g_B + (size_t)(n_base + row) * KDIM + kel + kb * 8);
            }
        }
    };
    auto load_stage = [&](int kc, int st) {
        #pragma unroll
        for (int i = 0; i < 4; i++) load_slice(kc, st, i);
        cp_commit();
    };

    // --- prologue: 2 stages in flight ---
    load_stage(0, 0);
    load_stage(1, 1);

    // --- mainloop: compute with DMA slices interleaved between s-steps ---
    int st = 0;
    for (int c = 0; c < NCHUNK; c++) {
        cp_wait<1>();
        __syncthreads();

        const bool do_load = (c + 2 < NCHUNK);
        const int  ld_st   = (c + 2) % STAGES;   // slot last read in iter c-1; safe after barrier

        const uint32_t sb = sbase + (uint32_t)st * STAGE_BYTES;
        #pragma unroll
        for (int s = 0; s < 4; s++) {                      // 4 k16 steps per chunk
            uint32_t af[2][4];
            ldsm4(af[0], sb + a_off + (uint32_t)s * 32u);
            ldsm4(af[1], sb + a_off + (uint32_t)s * 32u + 16u * ROWB);
            #pragma unroll
            for (int j = 0; j < 4; j++) {                  // 4 n16 pairs = 64 n
                uint32_t bf[4];
                ldsm4(bf, sb + A_STAGE + b_off + (uint32_t)s * 32u + (uint32_t)j * (16u * ROWB));
                mma_bf16(acc[0][2 * j],     af[0], bf);
                mma_bf16(acc[0][2 * j + 1], af[0], bf + 2);
                mma_bf16(acc[1][2 * j],     af[1], bf);
                mma_bf16(acc[1][2 * j + 1], af[1], bf + 2);
            }
            if (do_load) load_slice(c + 2, ld_st, s);      // 2 cp16/thread, spread evenly
        }
        cp_commit();   // exactly one commit per chunk (possibly empty group) keeps counting aligned

        st = (st + 1 == STAGES) ? 0 : st + 1;
    }

    // --- epilogue: y = clip(round_half_even(acc*alpha + bias)), stored as FLOAT32 ---
    const float alphav = *alpha_p;
    const int g = lane >> 2, t = lane & 3;
    #pragma unroll
    for (int i = 0; i < 2; i++) {
        const size_t row0 = (size_t)(m_base + wm * 32 + i * 16 + g);
        #pragma unroll
        for (int j = 0; j < 8; j++) {
            const int nc = n_base + wn * 64 + j * 8 + 2 * t;
            const float b0 = __ldg(bias + nc);
            const float b1 = __ldg(bias + nc + 1);
            const float* a = acc[i][j];
            int v0 = clip8(__float2int_rn(__fadd_rn(__fmul_rn(a[0], alphav), b0)));
            int v1 = clip8(__float2int_rn(__fadd_rn(__fmul_rn(a[1], alphav), b1)));
            int v2 = clip8(__float2int_rn(__fadd_rn(__fmul_rn(a[2], alphav), b0)));
            int v3 = clip8(__float2int_rn(__fadd_rn(__fmul_rn(a[3], alphav), b1)));
            float2 lo = make_float2((float)v0, (float)v1);
            float2 hi = make_float2((float)v2, (float)v3);
            *reinterpret_cast<float2*>(out + row0 * NDIM + nc) = lo;
            *reinterpret_cast<float2*>(out + (row0 + 8) * NDIM + nc) = hi;
        }
    }
}

// ---------------- host launch ----------------
extern "C" void kernel_launch(void* const* d_in, const int* in_sizes, int n_in,
                              void* d_out, int out_size) {
    const int*   x     = (const int*)d_in[0];
    const float* w     = (const float*)d_in[1];
    const float* bias  = (const float*)d_in[2];
    const float* alpha = (const float*)d_in[3];
    float*       out   = (float*)d_out;

    // single fused bf16 conversion launch (x + w)
    cvt_fused_kernel<<<CVT_XBLOCKS + CVT_WBLOCKS, 512>>>((const int4*)x, (const float4*)w);

    // set every call (non-stream API, capture-safe; no static guards per harness rules)
    cudaFuncSetAttribute(hmma_gemm_kernel,
                         cudaFuncAttributeMaxDynamicSharedMemorySize, SMEM_DYN);

    dim3 grid(NDIM / BN, MDIM / BM);   // (32, 64) = 2048 CTAs
    hmma_gemm_kernel<<<grid, THREADS, SMEM_DYN>>>(bias, alpha, out);
}

// round 13
// speedup vs baseline: 1.1976x; 1.0129x over previous
#include <cuda_runtime.h>
#include <cuda_bf16.h>
#include <cstdint>

// ---------------- problem dims ----------------
#define MDIM 8192
#define NDIM 4096
#define KDIM 4096

// ---------------- tiling ----------------
#define BM 128
#define BN 128
#define BK 64                              // K elements per chunk (bf16): 128B per row
#define ROWB 144                           // padded row stride (128B data + 16B pad)
#define STAGES 3
#define NCHUNK (KDIM / BK)                 // 64
#define A_STAGE (BM * ROWB)                // 18432 B
#define B_STAGE (BN * ROWB)                // 18432 B
#define STAGE_BYTES (A_STAGE + B_STAGE)    // 36864 B
#define SMEM_DYN (STAGES * STAGE_BYTES)    // 110592 B -> 2 CTAs/SM
#define THREADS 256                        // 8 warps, warp tile 32x64

// ---------------- bf16 staging (static device globals: no allocation) ----------------
__device__ __nv_bfloat16 g_A[(size_t)MDIM * KDIM];   // 64 MB
__device__ __nv_bfloat16 g_B[(size_t)NDIM * KDIM];   // 32 MB

// ---------------- PTX helpers (base-ISA: cp.async / ldmatrix / mma.sync bf16) -------
__device__ __forceinline__ uint32_t smem_u32(const void* p) {
    uint32_t a;
    asm("{ .reg .u64 t; cvta.to.shared.u64 t, %1; cvt.u32.u64 %0, t; }" : "=r"(a) : "l"(p));
    return a;
}

__device__ __forceinline__ void cp16(uint32_t dst, const void* src) {
    asm volatile("cp.async.cg.shared.global [%0], [%1], 16;" :: "r"(dst), "l"(src));
}
__device__ __forceinline__ void cp_commit() {
    asm volatile("cp.async.commit_group;" ::: "memory");
}
template <int N>
__device__ __forceinline__ void cp_wait() {
    asm volatile("cp.async.wait_group %0;" :: "n"(N) : "memory");
}

__device__ __forceinline__ void ldsm4(uint32_t* r, uint32_t addr) {
    asm volatile("ldmatrix.sync.aligned.m8n8.x4.shared.b16 {%0,%1,%2,%3}, [%4];"
                 : "=r"(r[0]), "=r"(r[1]), "=r"(r[2]), "=r"(r[3])
                 : "r"(addr));
}

__device__ __forceinline__ void mma_bf16(float* d, const uint32_t* a, const uint32_t* b) {
    asm volatile("mma.sync.aligned.m16n8k16.row.col.f32.bf16.bf16.f32 "
                 "{%0,%1,%2,%3}, {%4,%5,%6,%7}, {%8,%9}, {%0,%1,%2,%3};"
                 : "+f"(d[0]), "+f"(d[1]), "+f"(d[2]), "+f"(d[3])
                 : "r"(a[0]), "r"(a[1]), "r"(a[2]), "r"(a[3]), "r"(b[0]), "r"(b[1]));
}

// ---------------- fused conversion kernel (int8-valued -> bf16, exact) ----------------
#define CVT_XBLOCKS 4096
#define CVT_WBLOCKS 2048

__global__ void __launch_bounds__(512) cvt_fused_kernel(const int4* __restrict__ x,
                                                        const float4* __restrict__ w) {
    const unsigned b = blockIdx.x;
    if (b < CVT_XBLOCKS) {
        const size_t base = (size_t)b * 2048 + threadIdx.x;
        int4 v[4];
        #pragma unroll
        for (int k = 0; k < 4; k++) v[k] = x[base + (size_t)k * 512];
        #pragma unroll
        for (int k = 0; k < 4; k++) {
            union { __nv_bfloat162 h2[2]; uint2 u; } o;
            o.h2[0] = __floats2bfloat162_rn((float)v[k].x, (float)v[k].y);
            o.h2[1] = __floats2bfloat162_rn((float)v[k].z, (float)v[k].w);
            reinterpret_cast<uint2*>(g_A)[base + (size_t)k * 512] = o.u;
        }
    } else {
        const size_t base = (size_t)(b - CVT_XBLOCKS) * 2048 + threadIdx.x;
        float4 v[4];
        #pragma unroll
        for (int k = 0; k < 4; k++) v[k] = w[base + (size_t)k * 512];
        #pragma unroll
        for (int k = 0; k < 4; k++) {
            union { __nv_bfloat162 h2[2]; uint2 u; } o;
            o.h2[0] = __floats2bfloat162_rn(v[k].x, v[k].y);
            o.h2[1] = __floats2bfloat162_rn(v[k].z, v[k].w);
            reinterpret_cast<uint2*>(g_B)[base + (size_t)k * 512] = o.u;
        }
    }
}

// ---------------- GEMM kernel ----------------
__device__ __forceinline__ int clip8(int v) {
    return v < -128 ? -128 : (v > 127 ? 127 : v);
}

__global__ void __launch_bounds__(THREADS, 2)
hmma_gemm_kernel(const float* __restrict__ bias,
                 const float* __restrict__ alpha_p,
                 float* __restrict__ out) {
    extern __shared__ int8_t smem[];
    const uint32_t sbase = smem_u32(smem);

    const int tid  = threadIdx.x;
    const int lane = tid & 31;
    const int wid  = tid >> 5;       // 0..7
    const int wm   = wid >> 1;       // 0..3  (M warps, 32 rows each)
    const int wn   = wid & 1;        // 0..1  (N warps, 64 cols each)
    const int m_base = blockIdx.y * BM;
    const int n_base = blockIdx.x * BN;

    float acc[2][8][4];
    #pragma unroll
    for (int i = 0; i < 2; i++)
        #pragma unroll
        for (int j = 0; j < 8; j++)
            #pragma unroll
            for (int k = 0; k < 4; k++) acc[i][j][k] = 0.0f;

    // --- ldmatrix per-thread address components (padded 144B rows) ---
    const uint32_t arow   = (uint32_t)(wm * 32 + (lane & 15));
    const uint32_t akb_hi = (uint32_t)(lane >> 4);                 // 0/1 (8-element k half)
    const uint32_t a_off  = arow * ROWB + akb_hi * 16u;           // + s*32 + i*(16*ROWB)

    const uint32_t brow   = (uint32_t)(wn * 64 + (lane & 7) + ((lane >> 4) << 3));
    const uint32_t bkb_hi = (uint32_t)((lane >> 3) & 1);
    const uint32_t b_off  = brow * ROWB + bkb_hi * 16u;           // + s*32 + j*(16*ROWB)

    // --- one slice of a stage load: 2 chunks (of this thread's 8) ---
    auto load_slice = [&](int kc, int st, int slice) {
        const uint32_t sb = sbase + (uint32_t)st * STAGE_BYTES;
        const int kel = kc * BK;
        #pragma unroll
        for (int q = 0; q < 2; q++) {
            int ch = tid + THREADS * (2 * slice + q);
            if (ch < 1024) {   // A: 1024 chunks (uniform: slice<2)
                int row = ch >> 3, kb = ch & 7;
                cp16(sb + (uint32_t)row * ROWB + (uint32_t)kb * 16u,
                     g_A + (size_t)(m_base + row) * KDIM + kel + kb * 8);
            } else {           // B: 1024 chunks
                int c2 = ch - 1024;
                int row = c2 >> 3, kb = c2 & 7;
                cp16(sb + A_STAGE + (uint32_t)row * ROWB + (uint32_t)kb * 16u,
                     g_B + (size_t)(n_base + row) * KDIM + kel + kb * 8);
            }
        }
    };
    auto load_stage = [&](int kc, int st) {
        #pragma unroll
        for (int i = 0; i < 4; i++) load_slice(kc, st, i);
        cp_commit();
    };

    // --- prologue: 2 stages in flight ---
    load_stage(0, 0);
    load_stage(1, 1);

    // --- mainloop: compute with DMA slices interleaved + B-fragment double buffer ---
    int st = 0;
    for (int c = 0; c < NCHUNK; c++) {
        cp_wait<1>();
        __syncthreads();

        const bool do_load = (c + 2 < NCHUNK);
        const int  ld_st   = (c + 2) % STAGES;   // slot last read in iter c-1; safe after barrier

        const uint32_t sb = sbase + (uint32_t)st * STAGE_BYTES;
        #pragma unroll
        for (int s = 0; s < 4; s++) {                      // 4 k16 steps per chunk
            uint32_t af[2][4];
            ldsm4(af[0], sb + a_off + (uint32_t)s * 32u);
            ldsm4(af[1], sb + a_off + (uint32_t)s * 32u + 16u * ROWB);

            // B double buffer: load bf[j+1] before consuming bf[j]'s mma burst
            uint32_t bf[2][4];
            ldsm4(bf[0], sb + A_STAGE + b_off + (uint32_t)s * 32u);
            #pragma unroll
            for (int j = 0; j < 4; j++) {                  // 4 n16 pairs = 64 n
                if (j < 3)
                    ldsm4(bf[(j + 1) & 1],
                          sb + A_STAGE + b_off + (uint32_t)s * 32u + (uint32_t)(j + 1) * (16u * ROWB));
                const uint32_t* b = bf[j & 1];
                mma_bf16(acc[0][2 * j],     af[0], b);
                mma_bf16(acc[0][2 * j + 1], af[0], b + 2);
                mma_bf16(acc[1][2 * j],     af[1], b);
                mma_bf16(acc[1][2 * j + 1], af[1], b + 2);
            }
            if (do_load) load_slice(c + 2, ld_st, s);      // 2 cp16/thread, spread evenly
        }
        cp_commit();   // exactly one commit per chunk (possibly empty group) keeps counting aligned

        st = (st + 1 == STAGES) ? 0 : st + 1;
    }

    // --- epilogue: y = clip(round_half_even(acc*alpha + bias)), stored as FLOAT32 ---
    const float alphav = *alpha_p;
    const int g = lane >> 2, t = lane & 3;
    #pragma unroll
    for (int i = 0; i < 2; i++) {
        const size_t row0 = (size_t)(m_base + wm * 32 + i * 16 + g);
        #pragma unroll
        for (int j = 0; j < 8; j++) {
            const int nc = n_base + wn * 64 + j * 8 + 2 * t;
            const float b0 = __ldg(bias + nc);
            const float b1 = __ldg(bias + nc + 1);
            const float* a = acc[i][j];
            int v0 = clip8(__float2int_rn(__fadd_rn(__fmul_rn(a[0], alphav), b0)));
            int v1 = clip8(__float2int_rn(__fadd_rn(__fmul_rn(a[1], alphav), b1)));
            int v2 = clip8(__float2int_rn(__fadd_rn(__fmul_rn(a[2], alphav), b0)));
            int v3 = clip8(__float2int_rn(__fadd_rn(__fmul_rn(a[3], alphav), b1)));
            float2 lo = make_float2((float)v0, (float)v1);
            float2 hi = make_float2((float)v2, (float)v3);
            *reinterpret_cast<float2*>(out + row0 * NDIM + nc) = lo;
            *reinterpret_cast<float2*>(out + (row0 + 8) * NDIM + nc) = hi;
        }
    }
}

// ---------------- host launch ----------------
extern "C" void kernel_launch(void* const* d_in, const int* in_sizes, int n_in,
                              void* d_out, int out_size) {
    const int*   x     = (const int*)d_in[0];
    const float* w     = (const float*)d_in[1];
    const float* bias  = (const float*)d_in[2];
    const float* alpha = (const float*)d_in[3];
    float*       out   = (float*)d_out;

    // single fused bf16 conversion launch (x + w)
    cvt_fused_kernel<<<CVT_XBLOCKS + CVT_WBLOCKS, 512>>>((const int4*)x, (const float4*)w);

    // set every call (non-stream API, capture-safe; no static guards per harness rules)
    cudaFuncSetAttribute(hmma_gemm_kernel,
                         cudaFuncAttributeMaxDynamicSharedMemorySize, SMEM_DYN);

    dim3 grid(NDIM / BN, MDIM / BM);   // (32, 64) = 2048 CTAs
    hmma_gemm_kernel<<<grid, THREADS, SMEM_DYN>>>(bias, alpha, out);
}